// round 4
// baseline (speedup 1.0000x reference)
#include <cuda_runtime.h>
#include <cstdint>

#define N_ATOMS 500000
#define FDIM 128
#define TM 128
#define TN 128
#define BK 32
#define TOTAL_TILES 3910

__device__ __constant__ int d_OFFS[12] =
    {0, 10000, 110000, 260000, 410000, 490000, 495000, 497000, 498000, 499000, 499500, 500000};
__device__ __constant__ int d_TCUM[12] =
    {0, 79, 861, 2033, 3205, 3830, 3870, 3886, 3894, 3902, 3906, 3910};

// 1 if adjacency arrays are int64, 0 if int32. Set by probe_kernel.
__device__ int g_idx64;

// Parallel probe: lanes read odd int32 words of adj_deg2 (high halves if int64).
__global__ void probe_kernel(const int* __restrict__ a2_words)
{
    int v = a2_words[2 * threadIdx.x + 1];
    unsigned m = __ballot_sync(0xffffffffu, v != 0);
    if (threadIdx.x == 0) g_idx64 = (m == 0u) ? 1 : 0;
}

// -----------------------------------------------------------------------------
// TF32 helpers
// -----------------------------------------------------------------------------
__device__ __forceinline__ uint32_t f2tf32(float x) {
    uint32_t y;
    asm("cvt.rna.tf32.f32 %0, %1;" : "=r"(y) : "f"(x));
    return y;
}

__device__ __forceinline__ void mma_tf32(float* c, const uint32_t* a, const uint32_t* b) {
    asm volatile(
        "mma.sync.aligned.m16n8k8.row.col.f32.tf32.tf32.f32 "
        "{%0,%1,%2,%3}, {%4,%5,%6,%7}, {%8,%9}, {%0,%1,%2,%3};\n"
        : "+f"(c[0]), "+f"(c[1]), "+f"(c[2]), "+f"(c[3])
        : "r"(a[0]), "r"(a[1]), "r"(a[2]), "r"(a[3]), "r"(b[0]), "r"(b[1]));
}

// -----------------------------------------------------------------------------
// Fully fused kernel: gather (pass 0 A-load) + tf32 GEMM + bias + ReLU.
// 128x128 tile / block, 8 warps, warp tile 32(M) x 64(N), m16n8k8 atoms.
// Conflict-free smem strides: As[m][k] stride 36, Bs[k][n] stride 136.
// deg is uniform per block (tiles never cross segment boundaries).
// -----------------------------------------------------------------------------
#define AS_S 36
#define BS_S 136

__global__ __launch_bounds__(256, 2)
void fused_graphconv_kernel(
    const float* __restrict__ feat,
    const float* __restrict__ W,
    const float* __restrict__ b,
    float* __restrict__ out,
    const void* __restrict__ a1,  const void* __restrict__ a2,
    const void* __restrict__ a3,  const void* __restrict__ a4,
    const void* __restrict__ a5,  const void* __restrict__ a6,
    const void* __restrict__ a7,  const void* __restrict__ a8,
    const void* __restrict__ a9,  const void* __restrict__ a10)
{
    __shared__ uint32_t As[TM * AS_S];
    __shared__ uint32_t Bs[BK * BS_S];

    const int bt = blockIdx.x;
    int seg = 0;
#pragma unroll
    for (int s = 1; s <= 10; s++)
        if (bt >= d_TCUM[s]) seg = s;

    const int rs = d_OFFS[seg] + (bt - d_TCUM[seg]) * TM;
    const int re = d_OFFS[seg + 1];
    const int segstart = d_OFFS[seg];
    const int deg = seg;                 // degree == segment index (0 = no gather)

    const void* adj = nullptr;
    switch (seg) {
        case 1:  adj = a1;  break;  case 2:  adj = a2;  break;
        case 3:  adj = a3;  break;  case 4:  adj = a4;  break;
        case 5:  adj = a5;  break;  case 6:  adj = a6;  break;
        case 7:  adj = a7;  break;  case 8:  adj = a8;  break;
        case 9:  adj = a9;  break;  case 10: adj = a10; break;
        default: break;
    }
    const int idx64 = g_idx64;

    const int tid  = threadIdx.x;
    const int warp = tid >> 5;
    const int lane = tid & 31;
    const int wm = (warp >> 1) * 32;
    const int wn = (warp & 1) * 64;
    const int lq = lane >> 2;
    const int lr = lane & 3;

    // A/B loader indices
    const int m0 = tid >> 3;             // 0..31 (row group)
    const int k4 = (tid & 7) * 4;        // k offset (float4)
    const int bk0 = tid >> 5;            // 0..7
    const int bn4 = (tid & 31) * 4;

    float acc[2][8][4];
#pragma unroll
    for (int i = 0; i < 2; i++)
#pragma unroll
        for (int j = 0; j < 8; j++)
#pragma unroll
            for (int k = 0; k < 4; k++) acc[i][j][k] = 0.f;

    const int nPass = (seg == 0) ? 1 : 2;

    for (int pass = 0; pass < nPass; pass++) {
        const bool gather = (seg > 0) && (pass == 0);
        const float* Bsrc;
        if (seg == 0)       Bsrc = W + 20 * FDIM * TN;
        else if (pass == 0) Bsrc = W + (2 * (seg - 1)) * FDIM * TN;
        else                Bsrc = W + (2 * seg - 1) * FDIM * TN;

        for (int ko = 0; ko < FDIM; ko += BK) {
            // ---- B tile first (independent loads issue ahead of gather) ----
#pragma unroll
            for (int kk = 0; kk < 4; kk++) {
                int k = bk0 + kk * 8;
                float4 v = __ldg(reinterpret_cast<const float4*>(
                        Bsrc + (long long)(ko + k) * TN + bn4));
                uint4 t;
                t.x = f2tf32(v.x); t.y = f2tf32(v.y);
                t.z = f2tf32(v.z); t.w = f2tf32(v.w);
                *reinterpret_cast<uint4*>(&Bs[k * BS_S + bn4]) = t;
            }

            // ---- A tile: gather-sum (pass 0) or direct row load ----
            if (gather) {
#pragma unroll
                for (int rr = 0; rr < 4; rr++) {
                    int m = m0 + rr * 32;
                    int r = rs + m;
                    float4 s = make_float4(0.f, 0.f, 0.f, 0.f);
                    if (r < re) {
                        long long base = (long long)(r - segstart) * deg;
                        int j = 0;
                        // pairwise unroll for MLP
                        for (; j + 1 < deg; j += 2) {
                            long long nb0, nb1;
                            if (idx64) {
                                nb0 = __ldg(reinterpret_cast<const long long*>(adj) + base + j);
                                nb1 = __ldg(reinterpret_cast<const long long*>(adj) + base + j + 1);
                            } else {
                                nb0 = (long long)__ldg(reinterpret_cast<const int*>(adj) + base + j);
                                nb1 = (long long)__ldg(reinterpret_cast<const int*>(adj) + base + j + 1);
                            }
                            float4 v0 = __ldg(reinterpret_cast<const float4*>(
                                    feat + nb0 * FDIM + ko + k4));
                            float4 v1 = __ldg(reinterpret_cast<const float4*>(
                                    feat + nb1 * FDIM + ko + k4));
                            s.x += v0.x + v1.x; s.y += v0.y + v1.y;
                            s.z += v0.z + v1.z; s.w += v0.w + v1.w;
                        }
                        if (j < deg) {
                            long long nb;
                            if (idx64) nb = __ldg(reinterpret_cast<const long long*>(adj) + base + j);
                            else       nb = (long long)__ldg(reinterpret_cast<const int*>(adj) + base + j);
                            float4 v = __ldg(reinterpret_cast<const float4*>(
                                    feat + nb * FDIM + ko + k4));
                            s.x += v.x; s.y += v.y; s.z += v.z; s.w += v.w;
                        }
                    }
                    uint4 t;
                    t.x = f2tf32(s.x); t.y = f2tf32(s.y);
                    t.z = f2tf32(s.z); t.w = f2tf32(s.w);
                    *reinterpret_cast<uint4*>(&As[m * AS_S + k4]) = t;
                }
            } else {
#pragma unroll
                for (int rr = 0; rr < 4; rr++) {
                    int m = m0 + rr * 32;
                    int r = rs + m;
                    float4 v = make_float4(0.f, 0.f, 0.f, 0.f);
                    if (r < re)
                        v = __ldg(reinterpret_cast<const float4*>(
                                feat + (long long)r * FDIM + ko + k4));
                    uint4 t;
                    t.x = f2tf32(v.x); t.y = f2tf32(v.y);
                    t.z = f2tf32(v.z); t.w = f2tf32(v.w);
                    *reinterpret_cast<uint4*>(&As[m * AS_S + k4]) = t;
                }
            }
            __syncthreads();

#pragma unroll
            for (int ks = 0; ks < 4; ks++) {
                const int k0 = ks * 8;
                uint32_t af[2][4];
#pragma unroll
                for (int mi = 0; mi < 2; mi++) {
                    int r0 = wm + 16 * mi + lq;
                    int c0 = k0 + lr;
                    af[mi][0] = As[r0 * AS_S + c0];
                    af[mi][1] = As[(r0 + 8) * AS_S + c0];
                    af[mi][2] = As[r0 * AS_S + c0 + 4];
                    af[mi][3] = As[(r0 + 8) * AS_S + c0 + 4];
                }
                uint32_t bf[8][2];
#pragma unroll
                for (int nj = 0; nj < 8; nj++) {
                    int n0 = wn + 8 * nj + lq;
                    bf[nj][0] = Bs[(k0 + lr) * BS_S + n0];
                    bf[nj][1] = Bs[(k0 + lr + 4) * BS_S + n0];
                }
#pragma unroll
                for (int mi = 0; mi < 2; mi++)
#pragma unroll
                    for (int nj = 0; nj < 8; nj++)
                        mma_tf32(acc[mi][nj], af[mi], bf[nj]);
            }
            __syncthreads();
        }
    }

    // ---- bias + relu + store ----
    float2 bv[8];
#pragma unroll
    for (int nj = 0; nj < 8; nj++) {
        int n = wn + 8 * nj + 2 * lr;
        float2 bb;
        if (seg == 0) {
            bb.x = __ldg(b + 20 * TN + n);
            bb.y = __ldg(b + 20 * TN + n + 1);
        } else {
            const float* b0 = b + (2 * (seg - 1)) * TN;
            const float* b1 = b + (2 * seg - 1) * TN;
            bb.x = __ldg(b0 + n) + __ldg(b1 + n);
            bb.y = __ldg(b0 + n + 1) + __ldg(b1 + n + 1);
        }
        bv[nj] = bb;
    }

#pragma unroll
    for (int mi = 0; mi < 2; mi++) {
        int r0 = rs + wm + 16 * mi + lq;
#pragma unroll
        for (int nj = 0; nj < 8; nj++) {
            int col = wn + 8 * nj + 2 * lr;
            const float* c = acc[mi][nj];
            if (r0 < re) {
                float2 o;
                o.x = fmaxf(c[0] + bv[nj].x, 0.f);
                o.y = fmaxf(c[1] + bv[nj].y, 0.f);
                *reinterpret_cast<float2*>(out + (long long)r0 * TN + col) = o;
            }
            if (r0 + 8 < re) {
                float2 o;
                o.x = fmaxf(c[2] + bv[nj].x, 0.f);
                o.y = fmaxf(c[3] + bv[nj].y, 0.f);
                *reinterpret_cast<float2*>(out + (long long)(r0 + 8) * TN + col) = o;
            }
        }
    }
}

// -----------------------------------------------------------------------------
// Launch: identify inputs by unique element counts.
// -----------------------------------------------------------------------------
extern "C" void kernel_launch(void* const* d_in, const int* in_sizes, int n_in,
                              void* d_out, int out_size)
{
    const float* feat = nullptr;
    const float* W = nullptr;
    const float* b = nullptr;
    const void* adj[11] = {nullptr};

    for (int i = 0; i < n_in; i++) {
        switch (in_sizes[i]) {
            case 64000000: feat = (const float*)d_in[i]; break;
            case 344064:   W    = (const float*)d_in[i]; break;
            case 2688:     b    = (const float*)d_in[i]; break;
            case 100000:   adj[1]  = d_in[i]; break;
            case 300000:   adj[2]  = d_in[i]; break;
            case 450000:   adj[3]  = d_in[i]; break;
            case 320000:   adj[4]  = d_in[i]; break;
            case 25000:    adj[5]  = d_in[i]; break;
            case 12000:    adj[6]  = d_in[i]; break;
            case 7000:     adj[7]  = d_in[i]; break;
            case 8000:     adj[8]  = d_in[i]; break;
            case 4500:     adj[9]  = d_in[i]; break;
            case 5000:     adj[10] = d_in[i]; break;
            default: break;
        }
    }

    probe_kernel<<<1, 32>>>((const int*)adj[2]);

    fused_graphconv_kernel<<<TOTAL_TILES, 256>>>(
        feat, W, b, (float*)d_out,
        adj[1], adj[2], adj[3], adj[4], adj[5],
        adj[6], adj[7], adj[8], adj[9], adj[10]);
}

// round 5
// speedup vs baseline: 1.3685x; 1.3685x over previous
#include <cuda_runtime.h>
#include <cstdint>

#define N_ATOMS 500000
#define FDIM 128
#define TM 128
#define TN 128
#define TOTAL_TILES 3910

#define AS_S 132            // As row stride (words): bank spread 4, float4-aligned
#define BS_S 136            // Bs row stride (words): bank spread 8
#define AS_WORDS (TM * AS_S)              // 16896
#define BS_WORDS (32 * BS_S)              // 4352 per buffer
#define SMEM_BYTES ((AS_WORDS + 2 * BS_WORDS) * 4)   // 102400

__device__ __constant__ int d_OFFS[12] =
    {0, 10000, 110000, 260000, 410000, 490000, 495000, 497000, 498000, 499000, 499500, 500000};
__device__ __constant__ int d_TCUM[12] =
    {0, 79, 861, 2033, 3205, 3830, 3870, 3886, 3894, 3902, 3906, 3910};

__device__ int g_idx64;                       // adjacency width flag
__device__ uint32_t g_wtf32[21 * FDIM * TN];  // W pre-rounded to tf32 (5.5 MB)

__device__ __forceinline__ uint32_t f2tf32(float x) {
    uint32_t y;
    asm("cvt.rna.tf32.f32 %0, %1;" : "=r"(y) : "f"(x));
    return y;
}

__device__ __forceinline__ void mma_tf32(float* c, const uint32_t* a, const uint32_t* b) {
    asm volatile(
        "mma.sync.aligned.m16n8k8.row.col.f32.tf32.tf32.f32 "
        "{%0,%1,%2,%3}, {%4,%5,%6,%7}, {%8,%9}, {%0,%1,%2,%3};\n"
        : "+f"(c[0]), "+f"(c[1]), "+f"(c[2]), "+f"(c[3])
        : "r"(a[0]), "r"(a[1]), "r"(a[2]), "r"(a[3]), "r"(b[0]), "r"(b[1]));
}

__device__ __forceinline__ void cp_async16(uint32_t saddr, const void* g) {
    asm volatile("cp.async.cg.shared.global [%0], [%1], 16;" :: "r"(saddr), "l"(g));
}

// -----------------------------------------------------------------------------
// Prep: probe adjacency width + convert W to tf32.
// -----------------------------------------------------------------------------
__global__ void prep_kernel(const float* __restrict__ W, const int* __restrict__ a2w)
{
    int i = blockIdx.x * blockDim.x + threadIdx.x;
    if (i < 21 * FDIM * TN) g_wtf32[i] = f2tf32(W[i]);
    if (blockIdx.x == 0 && threadIdx.x < 32) {
        int v = a2w[2 * threadIdx.x + 1];
        unsigned m = __ballot_sync(0xffffffffu, v != 0);
        if (threadIdx.x == 0) g_idx64 = (m == 0u) ? 1 : 0;
    }
}

// -----------------------------------------------------------------------------
// Fused kernel: per-128-row-tile [gather full A] -> [4-step tf32 MMA with
// cp.async double-buffered B] x 2 passes -> bias + relu.
// 8 warps, warp tile 32x64, 2 CTAs/SM (100KB smem each).
// -----------------------------------------------------------------------------
__global__ __launch_bounds__(256, 2)
void fused_graphconv_kernel(
    const float* __restrict__ feat,
    const float* __restrict__ b,
    float* __restrict__ out,
    const void* __restrict__ a1,  const void* __restrict__ a2,
    const void* __restrict__ a3,  const void* __restrict__ a4,
    const void* __restrict__ a5,  const void* __restrict__ a6,
    const void* __restrict__ a7,  const void* __restrict__ a8,
    const void* __restrict__ a9,  const void* __restrict__ a10)
{
    extern __shared__ uint32_t smem[];
    uint32_t* As = smem;                 // [128][AS_S] tf32 bits
    uint32_t* Bs = smem + AS_WORDS;      // 2 x [32][BS_S]

    const int bt = blockIdx.x;
    int seg = 0;
#pragma unroll
    for (int s = 1; s <= 10; s++)
        if (bt >= d_TCUM[s]) seg = s;

    const int rs = d_OFFS[seg] + (bt - d_TCUM[seg]) * TM;
    const int re = d_OFFS[seg + 1];
    const int segstart = d_OFFS[seg];
    const int deg = seg;

    const void* adj = nullptr;
    switch (seg) {
        case 1:  adj = a1;  break;  case 2:  adj = a2;  break;
        case 3:  adj = a3;  break;  case 4:  adj = a4;  break;
        case 5:  adj = a5;  break;  case 6:  adj = a6;  break;
        case 7:  adj = a7;  break;  case 8:  adj = a8;  break;
        case 9:  adj = a9;  break;  case 10: adj = a10; break;
        default: break;
    }
    const int idx64 = g_idx64;

    const int tid  = threadIdx.x;
    const int warp = tid >> 5;
    const int lane = tid & 31;
    const int wm = (warp >> 1) * 32;
    const int wn = (warp & 1) * 64;
    const int lq = lane >> 2;
    const int lr = lane & 3;
    const int bk0 = tid >> 5;            // 0..7  (B loader k row)
    const int bn4 = (tid & 31) * 4;      // B loader n col (words)

    const int mat_rel  = (seg == 0) ? 20 : 2 * (seg - 1);
    const int mat_self = (seg == 0) ? 20 : 2 * seg - 1;
    const int nSteps = (seg == 0) ? 4 : 8;

    float acc[2][8][4];
#pragma unroll
    for (int i = 0; i < 2; i++)
#pragma unroll
        for (int j = 0; j < 8; j++)
#pragma unroll
            for (int k = 0; k < 4; k++) acc[i][j][k] = 0.f;

    // ---- B chunk issue: 32k x 128n of W_tf32[mat], k rows s*32.. ----
    auto issueB = [&](int mat, int s, int buf) {
        const uint32_t* src = g_wtf32 + (mat * FDIM + s * 32) * TN;
        uint32_t* dst = Bs + buf * BS_WORDS;
#pragma unroll
        for (int kk = 0; kk < 4; kk++) {
            int k = bk0 + kk * 8;
            uint32_t sa = (uint32_t)__cvta_generic_to_shared(dst + k * BS_S + bn4);
            cp_async16(sa, src + k * TN + bn4);
        }
        asm volatile("cp.async.commit_group;" ::: "memory");
    };

    // ---- A phase: gather-sum full 128-wide rows (one warp = one row) ----
    auto loadA_gather = [&]() {
        const int rbase = warp * 16;
        for (int i = 0; i < 16; i += 2) {
            int m0 = rbase + i;
            int r0 = rs + m0, r1 = r0 + 1;
            bool gd0 = r0 < re, gd1 = r1 < re;
            long long b0 = (long long)(gd0 ? (r0 - segstart) : 0) * deg;
            long long b1 = (long long)(gd1 ? (r1 - segstart) : 0) * deg;
            float4 s0 = make_float4(0.f, 0.f, 0.f, 0.f);
            float4 s1 = make_float4(0.f, 0.f, 0.f, 0.f);
#pragma unroll 2
            for (int j = 0; j < deg; j++) {
                long long nb0, nb1;
                if (idx64) {
                    nb0 = __ldg(reinterpret_cast<const long long*>(adj) + b0 + j);
                    nb1 = __ldg(reinterpret_cast<const long long*>(adj) + b1 + j);
                } else {
                    nb0 = (long long)__ldg(reinterpret_cast<const int*>(adj) + b0 + j);
                    nb1 = (long long)__ldg(reinterpret_cast<const int*>(adj) + b1 + j);
                }
                float4 v0 = __ldg(reinterpret_cast<const float4*>(feat + nb0 * FDIM) + lane);
                float4 v1 = __ldg(reinterpret_cast<const float4*>(feat + nb1 * FDIM) + lane);
                s0.x += v0.x; s0.y += v0.y; s0.z += v0.z; s0.w += v0.w;
                s1.x += v1.x; s1.y += v1.y; s1.z += v1.z; s1.w += v1.w;
            }
            if (!gd0) s0 = make_float4(0.f, 0.f, 0.f, 0.f);
            if (!gd1) s1 = make_float4(0.f, 0.f, 0.f, 0.f);
            uint4 t0, t1;
            t0.x = f2tf32(s0.x); t0.y = f2tf32(s0.y); t0.z = f2tf32(s0.z); t0.w = f2tf32(s0.w);
            t1.x = f2tf32(s1.x); t1.y = f2tf32(s1.y); t1.z = f2tf32(s1.z); t1.w = f2tf32(s1.w);
            *reinterpret_cast<uint4*>(&As[m0 * AS_S + lane * 4]) = t0;
            *reinterpret_cast<uint4*>(&As[(m0 + 1) * AS_S + lane * 4]) = t1;
        }
    };

    // ---- A phase: direct self rows ----
    auto loadA_self = [&]() {
        const int rbase = warp * 16;
        for (int i = 0; i < 16; i += 2) {
            int m0 = rbase + i;
            int r0 = rs + m0, r1 = r0 + 1;
            float4 s0 = make_float4(0.f, 0.f, 0.f, 0.f);
            float4 s1 = make_float4(0.f, 0.f, 0.f, 0.f);
            if (r0 < re) s0 = __ldg(reinterpret_cast<const float4*>(feat + (long long)r0 * FDIM) + lane);
            if (r1 < re) s1 = __ldg(reinterpret_cast<const float4*>(feat + (long long)r1 * FDIM) + lane);
            uint4 t0, t1;
            t0.x = f2tf32(s0.x); t0.y = f2tf32(s0.y); t0.z = f2tf32(s0.z); t0.w = f2tf32(s0.w);
            t1.x = f2tf32(s1.x); t1.y = f2tf32(s1.y); t1.z = f2tf32(s1.z); t1.w = f2tf32(s1.w);
            *reinterpret_cast<uint4*>(&As[m0 * AS_S + lane * 4]) = t0;
            *reinterpret_cast<uint4*>(&As[(m0 + 1) * AS_S + lane * 4]) = t1;
        }
    };

    // ---- prologue: B(0) in flight during the (long) first A phase ----
    issueB(mat_rel, 0, 0);
    if (seg > 0) loadA_gather(); else loadA_self();

    for (int t = 0; t < nSteps; t++) {
        if (t == 4) {
            __syncthreads();           // all warps done reading As (pass 0)
            loadA_self();              // overlaps with in-flight B(4)
        }
        asm volatile("cp.async.wait_group 0;" ::: "memory");
        __syncthreads();               // B(t) visible; MMA(t-1) complete
        if (t + 1 < nSteps) {
            int nt = t + 1;
            issueB(nt < 4 ? mat_rel : mat_self, nt & 3, nt & 1);
        }
        // ---- MMA step t: A cols [ (t&3)*32 .. +32 ), B buffer t&1 ----
        const uint32_t* Bbuf = Bs + (t & 1) * BS_WORDS;
        const int koA = (t & 3) * 32;
#pragma unroll
        for (int ks = 0; ks < 4; ks++) {
            const int ka = koA + ks * 8;
            const int kb = ks * 8;
            uint32_t af[2][4];
#pragma unroll
            for (int mi = 0; mi < 2; mi++) {
                int r0 = wm + 16 * mi + lq;
                int c0 = ka + lr;
                af[mi][0] = As[r0 * AS_S + c0];
                af[mi][1] = As[(r0 + 8) * AS_S + c0];
                af[mi][2] = As[r0 * AS_S + c0 + 4];
                af[mi][3] = As[(r0 + 8) * AS_S + c0 + 4];
            }
            uint32_t bf[8][2];
#pragma unroll
            for (int nj = 0; nj < 8; nj++) {
                int n0 = wn + 8 * nj + lq;
                bf[nj][0] = Bbuf[(kb + lr) * BS_S + n0];
                bf[nj][1] = Bbuf[(kb + lr + 4) * BS_S + n0];
            }
#pragma unroll
            for (int mi = 0; mi < 2; mi++)
#pragma unroll
                for (int nj = 0; nj < 8; nj++)
                    mma_tf32(acc[mi][nj], af[mi], bf[nj]);
        }
    }

    // ---- bias + relu + store ----
    float2 bv[8];
#pragma unroll
    for (int nj = 0; nj < 8; nj++) {
        int n = wn + 8 * nj + 2 * lr;
        float2 bb;
        if (seg == 0) {
            bb.x = __ldg(b + 20 * TN + n);
            bb.y = __ldg(b + 20 * TN + n + 1);
        } else {
            const float* b0 = b + (2 * (seg - 1)) * TN;
            const float* b1 = b + (2 * seg - 1) * TN;
            bb.x = __ldg(b0 + n) + __ldg(b1 + n);
            bb.y = __ldg(b0 + n + 1) + __ldg(b1 + n + 1);
        }
        bv[nj] = bb;
    }

#pragma unroll
    for (int mi = 0; mi < 2; mi++) {
        int r0 = rs + wm + 16 * mi + lq;
#pragma unroll
        for (int nj = 0; nj < 8; nj++) {
            int col = wn + 8 * nj + 2 * lr;
            const float* c = acc[mi][nj];
            if (r0 < re) {
                float2 o;
                o.x = fmaxf(c[0] + bv[nj].x, 0.f);
                o.y = fmaxf(c[1] + bv[nj].y, 0.f);
                *reinterpret_cast<float2*>(out + (long long)r0 * TN + col) = o;
            }
            if (r0 + 8 < re) {
                float2 o;
                o.x = fmaxf(c[2] + bv[nj].x, 0.f);
                o.y = fmaxf(c[3] + bv[nj].y, 0.f);
                *reinterpret_cast<float2*>(out + (long long)(r0 + 8) * TN + col) = o;
            }
        }
    }
}

// -----------------------------------------------------------------------------
// Launch
// -----------------------------------------------------------------------------
extern "C" void kernel_launch(void* const* d_in, const int* in_sizes, int n_in,
                              void* d_out, int out_size)
{
    const float* feat = nullptr;
    const float* W = nullptr;
    const float* b = nullptr;
    const void* adj[11] = {nullptr};

    for (int i = 0; i < n_in; i++) {
        switch (in_sizes[i]) {
            case 64000000: feat = (const float*)d_in[i]; break;
            case 344064:   W    = (const float*)d_in[i]; break;
            case 2688:     b    = (const float*)d_in[i]; break;
            case 100000:   adj[1]  = d_in[i]; break;
            case 300000:   adj[2]  = d_in[i]; break;
            case 450000:   adj[3]  = d_in[i]; break;
            case 320000:   adj[4]  = d_in[i]; break;
            case 25000:    adj[5]  = d_in[i]; break;
            case 12000:    adj[6]  = d_in[i]; break;
            case 7000:     adj[7]  = d_in[i]; break;
            case 8000:     adj[8]  = d_in[i]; break;
            case 4500:     adj[9]  = d_in[i]; break;
            case 5000:     adj[10] = d_in[i]; break;
            default: break;
        }
    }

    static bool attr_set = false;
    if (!attr_set) {
        cudaFuncSetAttribute(fused_graphconv_kernel,
                             cudaFuncAttributeMaxDynamicSharedMemorySize, SMEM_BYTES);
        attr_set = true;
    }

    prep_kernel<<<(21 * FDIM * TN + 255) / 256, 256>>>(W, (const int*)adj[2]);

    fused_graphconv_kernel<<<TOTAL_TILES, 256, SMEM_BYTES>>>(
        feat, b, (float*)d_out,
        adj[1], adj[2], adj[3], adj[4], adj[5],
        adj[6], adj[7], adj[8], adj[9], adj[10]);
}

// round 6
// speedup vs baseline: 1.5188x; 1.1099x over previous
#include <cuda_runtime.h>
#include <cstdint>

#define N_ATOMS 500000
#define FDIM 128
#define TM 64
#define TN 128
#define TOTAL_TILES 7817

#define AS_S 132            // As row stride (words)
#define BS_S 136            // Bs row stride (words)
#define AS_WORDS (TM * AS_S)              // 8448
#define BS_WORDS (32 * BS_S)              // 4352 per buffer
#define SMEM_BYTES ((AS_WORDS + 2 * BS_WORDS) * 4)   // 68608

__device__ __constant__ int d_OFFS[12] =
    {0, 10000, 110000, 260000, 410000, 490000, 495000, 497000, 498000, 499000, 499500, 500000};
__device__ __constant__ int d_TCUM[12] =
    {0, 157, 1720, 4064, 6408, 7658, 7737, 7769, 7785, 7801, 7809, 7817};

__device__ int g_idx64;                       // adjacency width flag
__device__ uint32_t g_wtf32[21 * FDIM * TN];  // W pre-rounded to tf32

__device__ __forceinline__ uint32_t f2tf32(float x) {
    uint32_t y;
    asm("cvt.rna.tf32.f32 %0, %1;" : "=r"(y) : "f"(x));
    return y;
}

__device__ __forceinline__ void mma_tf32(float* c, const uint32_t* a, const uint32_t* b) {
    asm volatile(
        "mma.sync.aligned.m16n8k8.row.col.f32.tf32.tf32.f32 "
        "{%0,%1,%2,%3}, {%4,%5,%6,%7}, {%8,%9}, {%0,%1,%2,%3};\n"
        : "+f"(c[0]), "+f"(c[1]), "+f"(c[2]), "+f"(c[3])
        : "r"(a[0]), "r"(a[1]), "r"(a[2]), "r"(a[3]), "r"(b[0]), "r"(b[1]));
}

__device__ __forceinline__ void cp_async16(uint32_t saddr, const void* g) {
    asm volatile("cp.async.cg.shared.global [%0], [%1], 16;" :: "r"(saddr), "l"(g));
}

// -----------------------------------------------------------------------------
// Prep: probe adjacency width + convert W to tf32.
// -----------------------------------------------------------------------------
__global__ void prep_kernel(const float* __restrict__ W, const int* __restrict__ a2w)
{
    int i = blockIdx.x * blockDim.x + threadIdx.x;
    if (i < 21 * FDIM * TN) g_wtf32[i] = f2tf32(W[i]);
    if (blockIdx.x == 0 && threadIdx.x < 32) {
        int v = a2w[2 * threadIdx.x + 1];
        unsigned m = __ballot_sync(0xffffffffu, v != 0);
        if (threadIdx.x == 0) g_idx64 = (m == 0u) ? 1 : 0;
    }
}

// -----------------------------------------------------------------------------
// Fused kernel: 64x128 output tile / CTA, 8 warps (warp tile 32x32),
// 3 CTAs/SM. Per pass: [gather/load full 64x128 A] -> [4 MMA steps with
// cp.async double-buffered B]. K=256 total (rel + self). bias + relu epilogue.
// -----------------------------------------------------------------------------
__global__ __launch_bounds__(256, 3)
void fused_graphconv_kernel(
    const float* __restrict__ feat,
    const float* __restrict__ b,
    float* __restrict__ out,
    const void* __restrict__ a1,  const void* __restrict__ a2,
    const void* __restrict__ a3,  const void* __restrict__ a4,
    const void* __restrict__ a5,  const void* __restrict__ a6,
    const void* __restrict__ a7,  const void* __restrict__ a8,
    const void* __restrict__ a9,  const void* __restrict__ a10)
{
    extern __shared__ uint32_t smem[];
    uint32_t* As = smem;                 // [64][AS_S] tf32 bits
    uint32_t* Bs = smem + AS_WORDS;      // 2 x [32][BS_S]

    const int bt = blockIdx.x;
    int seg = 0;
#pragma unroll
    for (int s = 1; s <= 10; s++)
        if (bt >= d_TCUM[s]) seg = s;

    const int rs = d_OFFS[seg] + (bt - d_TCUM[seg]) * TM;
    const int re = d_OFFS[seg + 1];
    const int segstart = d_OFFS[seg];
    const int deg = seg;

    const void* adj = nullptr;
    switch (seg) {
        case 1:  adj = a1;  break;  case 2:  adj = a2;  break;
        case 3:  adj = a3;  break;  case 4:  adj = a4;  break;
        case 5:  adj = a5;  break;  case 6:  adj = a6;  break;
        case 7:  adj = a7;  break;  case 8:  adj = a8;  break;
        case 9:  adj = a9;  break;  case 10: adj = a10; break;
        default: break;
    }
    const int idx64 = g_idx64;

    const int tid  = threadIdx.x;
    const int warp = tid >> 5;
    const int lane = tid & 31;
    const int wm = (warp >> 2) * 32;     // 2 M groups
    const int wn = (warp & 3) * 32;      // 4 N groups
    const int lq = lane >> 2;
    const int lr = lane & 3;
    const int bk0 = tid >> 5;            // B loader k row
    const int bn4 = (tid & 31) * 4;      // B loader n col (words)

    const int mat_rel  = (seg == 0) ? 20 : 2 * (seg - 1);
    const int mat_self = (seg == 0) ? 20 : 2 * seg - 1;
    const int nSteps = (seg == 0) ? 4 : 8;

    // ---- B chunk issue: 32k x 128n of W_tf32[mat] ----
    auto issueB = [&](int mat, int s, int buf) {
        const uint32_t* src = g_wtf32 + (mat * FDIM + s * 32) * TN;
        uint32_t* dst = Bs + buf * BS_WORDS;
#pragma unroll
        for (int kk = 0; kk < 4; kk++) {
            int k = bk0 + kk * 8;
            uint32_t sa = (uint32_t)__cvta_generic_to_shared(dst + k * BS_S + bn4);
            cp_async16(sa, src + k * TN + bn4);
        }
        asm volatile("cp.async.commit_group;" ::: "memory");
    };

    // ---- gather-sum A: 8 rows per warp, 4-row unroll for MLP ----
    auto loadA_gather = [&]() {
        const int rbase = warp * 8;
        for (int g = 0; g < 8; g += 4) {
            int m0 = rbase + g;
            float4 s0 = make_float4(0.f,0.f,0.f,0.f), s1 = s0, s2 = s0, s3 = s0;
            int r = rs + m0;
            bool gd0 = r < re, gd1 = r + 1 < re, gd2 = r + 2 < re, gd3 = r + 3 < re;
            long long b0 = (long long)(gd0 ? (r     - segstart) : 0) * deg;
            long long b1 = (long long)(gd1 ? (r + 1 - segstart) : 0) * deg;
            long long b2 = (long long)(gd2 ? (r + 2 - segstart) : 0) * deg;
            long long b3 = (long long)(gd3 ? (r + 3 - segstart) : 0) * deg;
            for (int j = 0; j < deg; j++) {
                long long n0, n1, n2, n3;
                if (idx64) {
                    n0 = __ldg((const long long*)adj + b0 + j);
                    n1 = __ldg((const long long*)adj + b1 + j);
                    n2 = __ldg((const long long*)adj + b2 + j);
                    n3 = __ldg((const long long*)adj + b3 + j);
                } else {
                    n0 = (long long)__ldg((const int*)adj + b0 + j);
                    n1 = (long long)__ldg((const int*)adj + b1 + j);
                    n2 = (long long)__ldg((const int*)adj + b2 + j);
                    n3 = (long long)__ldg((const int*)adj + b3 + j);
                }
                float4 v0 = __ldg((const float4*)(feat + n0 * FDIM) + lane);
                float4 v1 = __ldg((const float4*)(feat + n1 * FDIM) + lane);
                float4 v2 = __ldg((const float4*)(feat + n2 * FDIM) + lane);
                float4 v3 = __ldg((const float4*)(feat + n3 * FDIM) + lane);
                s0.x += v0.x; s0.y += v0.y; s0.z += v0.z; s0.w += v0.w;
                s1.x += v1.x; s1.y += v1.y; s1.z += v1.z; s1.w += v1.w;
                s2.x += v2.x; s2.y += v2.y; s2.z += v2.z; s2.w += v2.w;
                s3.x += v3.x; s3.y += v3.y; s3.z += v3.z; s3.w += v3.w;
            }
            if (!gd0) s0 = make_float4(0.f,0.f,0.f,0.f);
            if (!gd1) s1 = make_float4(0.f,0.f,0.f,0.f);
            if (!gd2) s2 = make_float4(0.f,0.f,0.f,0.f);
            if (!gd3) s3 = make_float4(0.f,0.f,0.f,0.f);
            uint4 t;
            t.x=f2tf32(s0.x); t.y=f2tf32(s0.y); t.z=f2tf32(s0.z); t.w=f2tf32(s0.w);
            *reinterpret_cast<uint4*>(&As[(m0+0) * AS_S + lane * 4]) = t;
            t.x=f2tf32(s1.x); t.y=f2tf32(s1.y); t.z=f2tf32(s1.z); t.w=f2tf32(s1.w);
            *reinterpret_cast<uint4*>(&As[(m0+1) * AS_S + lane * 4]) = t;
            t.x=f2tf32(s2.x); t.y=f2tf32(s2.y); t.z=f2tf32(s2.z); t.w=f2tf32(s2.w);
            *reinterpret_cast<uint4*>(&As[(m0+2) * AS_S + lane * 4]) = t;
            t.x=f2tf32(s3.x); t.y=f2tf32(s3.y); t.z=f2tf32(s3.z); t.w=f2tf32(s3.w);
            *reinterpret_cast<uint4*>(&As[(m0+3) * AS_S + lane * 4]) = t;
        }
    };

    auto loadA_self = [&]() {
        const int rbase = warp * 8;
#pragma unroll
        for (int g = 0; g < 8; g += 4) {
            int m0 = rbase + g;
            float4 v[4];
#pragma unroll
            for (int q = 0; q < 4; q++) {
                int r = rs + m0 + q;
                v[q] = make_float4(0.f,0.f,0.f,0.f);
                if (r < re)
                    v[q] = __ldg((const float4*)(feat + (long long)r * FDIM) + lane);
            }
#pragma unroll
            for (int q = 0; q < 4; q++) {
                uint4 t;
                t.x=f2tf32(v[q].x); t.y=f2tf32(v[q].y);
                t.z=f2tf32(v[q].z); t.w=f2tf32(v[q].w);
                *reinterpret_cast<uint4*>(&As[(m0+q) * AS_S + lane * 4]) = t;
            }
        }
    };

    // ---- prologue: B(0) in flight during the first A phase ----
    issueB(mat_rel, 0, 0);
    if (seg > 0) loadA_gather(); else loadA_self();

    // acc init AFTER gather (keeps gather register pressure low)
    float acc[2][4][4];
#pragma unroll
    for (int i = 0; i < 2; i++)
#pragma unroll
        for (int j = 0; j < 4; j++)
#pragma unroll
            for (int k = 0; k < 4; k++) acc[i][j][k] = 0.f;

    for (int t = 0; t < nSteps; t++) {
        if (t == 4) {
            __syncthreads();           // all warps done reading As (pass 0)
            loadA_self();
        }
        asm volatile("cp.async.wait_group 0;" ::: "memory");
        __syncthreads();
        if (t + 1 < nSteps) {
            int nt = t + 1;
            issueB(nt < 4 ? mat_rel : mat_self, nt & 3, nt & 1);
        }
        const uint32_t* Bbuf = Bs + (t & 1) * BS_WORDS;
        const int koA = (t & 3) * 32;
#pragma unroll
        for (int ks = 0; ks < 4; ks++) {
            const int ka = koA + ks * 8;
            const int kb = ks * 8;
            uint32_t af[2][4];
#pragma unroll
            for (int mi = 0; mi < 2; mi++) {
                int r0 = wm + 16 * mi + lq;
                int c0 = ka + lr;
                af[mi][0] = As[r0 * AS_S + c0];
                af[mi][1] = As[(r0 + 8) * AS_S + c0];
                af[mi][2] = As[r0 * AS_S + c0 + 4];
                af[mi][3] = As[(r0 + 8) * AS_S + c0 + 4];
            }
            uint32_t bf[4][2];
#pragma unroll
            for (int nj = 0; nj < 4; nj++) {
                int n0 = wn + 8 * nj + lq;
                bf[nj][0] = Bbuf[(kb + lr) * BS_S + n0];
                bf[nj][1] = Bbuf[(kb + lr + 4) * BS_S + n0];
            }
#pragma unroll
            for (int mi = 0; mi < 2; mi++)
#pragma unroll
                for (int nj = 0; nj < 4; nj++)
                    mma_tf32(acc[mi][nj], af[mi], bf[nj]);
        }
    }

    // ---- bias + relu + store ----
    float2 bv[4];
#pragma unroll
    for (int nj = 0; nj < 4; nj++) {
        int n = wn + 8 * nj + 2 * lr;
        float2 bb;
        if (seg == 0) {
            bb.x = __ldg(b + 20 * TN + n);
            bb.y = __ldg(b + 20 * TN + n + 1);
        } else {
            const float* b0 = b + (2 * (seg - 1)) * TN;
            const float* b1 = b + (2 * seg - 1) * TN;
            bb.x = __ldg(b0 + n) + __ldg(b1 + n);
            bb.y = __ldg(b0 + n + 1) + __ldg(b1 + n + 1);
        }
        bv[nj] = bb;
    }

#pragma unroll
    for (int mi = 0; mi < 2; mi++) {
        int r0 = rs + wm + 16 * mi + lq;
#pragma unroll
        for (int nj = 0; nj < 4; nj++) {
            int col = wn + 8 * nj + 2 * lr;
            const float* c = acc[mi][nj];
            if (r0 < re) {
                float2 o;
                o.x = fmaxf(c[0] + bv[nj].x, 0.f);
                o.y = fmaxf(c[1] + bv[nj].y, 0.f);
                *reinterpret_cast<float2*>(out + (long long)r0 * TN + col) = o;
            }
            if (r0 + 8 < re) {
                float2 o;
                o.x = fmaxf(c[2] + bv[nj].x, 0.f);
                o.y = fmaxf(c[3] + bv[nj].y, 0.f);
                *reinterpret_cast<float2*>(out + (long long)(r0 + 8) * TN + col) = o;
            }
        }
    }
}

// -----------------------------------------------------------------------------
// Launch
// -----------------------------------------------------------------------------
extern "C" void kernel_launch(void* const* d_in, const int* in_sizes, int n_in,
                              void* d_out, int out_size)
{
    const float* feat = nullptr;
    const float* W = nullptr;
    const float* b = nullptr;
    const void* adj[11] = {nullptr};

    for (int i = 0; i < n_in; i++) {
        switch (in_sizes[i]) {
            case 64000000: feat = (const float*)d_in[i]; break;
            case 344064:   W    = (const float*)d_in[i]; break;
            case 2688:     b    = (const float*)d_in[i]; break;
            case 100000:   adj[1]  = d_in[i]; break;
            case 300000:   adj[2]  = d_in[i]; break;
            case 450000:   adj[3]  = d_in[i]; break;
            case 320000:   adj[4]  = d_in[i]; break;
            case 25000:    adj[5]  = d_in[i]; break;
            case 12000:    adj[6]  = d_in[i]; break;
            case 7000:     adj[7]  = d_in[i]; break;
            case 8000:     adj[8]  = d_in[i]; break;
            case 4500:     adj[9]  = d_in[i]; break;
            case 5000:     adj[10] = d_in[i]; break;
            default: break;
        }
    }

    static bool attr_set = false;
    if (!attr_set) {
        cudaFuncSetAttribute(fused_graphconv_kernel,
                             cudaFuncAttributeMaxDynamicSharedMemorySize, SMEM_BYTES);
        attr_set = true;
    }

    prep_kernel<<<(21 * FDIM * TN + 255) / 256, 256>>>(W, (const int*)adj[2]);

    fused_graphconv_kernel<<<TOTAL_TILES, 256, SMEM_BYTES>>>(
        feat, b, (float*)d_out,
        adj[1], adj[2], adj[3], adj[4], adj[5],
        adj[6], adj[7], adj[8], adj[9], adj[10]);
}

// round 7
// speedup vs baseline: 1.5356x; 1.0111x over previous
#include <cuda_runtime.h>
#include <cstdint>

#define N_ATOMS 500000
#define FDIM 128
#define TM 64
#define TN 128
#define TOTAL_TILES 7817

#define AS_S 132            // As row stride (words)
#define BS_S 136            // Bs row stride (words)
#define AS_WORDS (TM * AS_S)
#define BS_WORDS (32 * BS_S)
#define SMEM_BYTES ((AS_WORDS + 2 * BS_WORDS) * 4)   // 68608

__device__ __constant__ int d_OFFS[12] =
    {0, 10000, 110000, 260000, 410000, 490000, 495000, 497000, 498000, 499000, 499500, 500000};
__device__ __constant__ int d_TCUM[12] =
    {0, 157, 1720, 4064, 6408, 7658, 7737, 7769, 7785, 7801, 7809, 7817};

__device__ int g_idx64;
__device__ uint32_t g_wtf32[21 * FDIM * TN];

__device__ __forceinline__ uint32_t f2tf32(float x) {
    uint32_t y;
    asm("cvt.rna.tf32.f32 %0, %1;" : "=r"(y) : "f"(x));
    return y;
}

__device__ __forceinline__ void mma_tf32(float* c, const uint32_t* a, const uint32_t* b) {
    asm volatile(
        "mma.sync.aligned.m16n8k8.row.col.f32.tf32.tf32.f32 "
        "{%0,%1,%2,%3}, {%4,%5,%6,%7}, {%8,%9}, {%0,%1,%2,%3};\n"
        : "+f"(c[0]), "+f"(c[1]), "+f"(c[2]), "+f"(c[3])
        : "r"(a[0]), "r"(a[1]), "r"(a[2]), "r"(a[3]), "r"(b[0]), "r"(b[1]));
}

__device__ __forceinline__ void cp_async16(uint32_t saddr, const void* g) {
    asm volatile("cp.async.cg.shared.global [%0], [%1], 16;" :: "r"(saddr), "l"(g));
}

__global__ void prep_kernel(const float* __restrict__ W, const int* __restrict__ a2w)
{
    int i = blockIdx.x * blockDim.x + threadIdx.x;
    if (i < 21 * FDIM * TN) g_wtf32[i] = f2tf32(W[i]);
    if (blockIdx.x == 0 && threadIdx.x < 32) {
        int v = a2w[2 * threadIdx.x + 1];
        unsigned m = __ballot_sync(0xffffffffu, v != 0);
        if (threadIdx.x == 0) g_idx64 = (m == 0u) ? 1 : 0;
    }
}

// ---- 8-rows-in-flight gather, degree known at compile time (int32 indices) ----
template<int DEG>
__device__ __forceinline__ void gather8(
    const float* __restrict__ feat, const int* __restrict__ adj,
    int rs, int re, int segstart, int warp, int lane, uint32_t* As)
{
    const int rbase = warp * 8;
    int base[8];
    bool gd[8];
#pragma unroll
    for (int q = 0; q < 8; q++) {
        int r = rs + rbase + q;
        gd[q] = r < re;
        base[q] = (gd[q] ? (r - segstart) : 0) * DEG;
    }
    float4 s[8];
#pragma unroll
    for (int q = 0; q < 8; q++) s[q] = make_float4(0.f, 0.f, 0.f, 0.f);

#pragma unroll
    for (int j = 0; j < DEG; j++) {
        int n[8];
#pragma unroll
        for (int q = 0; q < 8; q++) n[q] = __ldg(adj + base[q] + j);
        float4 v[8];
#pragma unroll
        for (int q = 0; q < 8; q++)
            v[q] = __ldg(reinterpret_cast<const float4*>(feat + (long long)n[q] * FDIM) + lane);
#pragma unroll
        for (int q = 0; q < 8; q++) {
            s[q].x += v[q].x; s[q].y += v[q].y;
            s[q].z += v[q].z; s[q].w += v[q].w;
        }
    }
#pragma unroll
    for (int q = 0; q < 8; q++) {
        uint4 t;
        if (!gd[q]) s[q] = make_float4(0.f, 0.f, 0.f, 0.f);
        t.x = f2tf32(s[q].x); t.y = f2tf32(s[q].y);
        t.z = f2tf32(s[q].z); t.w = f2tf32(s[q].w);
        *reinterpret_cast<uint4*>(&As[(rbase + q) * AS_S + lane * 4]) = t;
    }
}

// ---- generic fallback (int64 indices, runtime degree) ----
__device__ __noinline__ void gather_generic(
    const float* __restrict__ feat, const long long* __restrict__ adj, int deg,
    int rs, int re, int segstart, int warp, int lane, uint32_t* As)
{
    const int rbase = warp * 8;
    for (int g = 0; g < 8; g += 4) {
        float4 s[4];
        long long base[4];
        bool gd[4];
#pragma unroll
        for (int q = 0; q < 4; q++) {
            int r = rs + rbase + g + q;
            gd[q] = r < re;
            base[q] = (long long)(gd[q] ? (r - segstart) : 0) * deg;
            s[q] = make_float4(0.f, 0.f, 0.f, 0.f);
        }
        for (int j = 0; j < deg; j++) {
#pragma unroll
            for (int q = 0; q < 4; q++) {
                long long nb = __ldg(adj + base[q] + j);
                float4 v = __ldg(reinterpret_cast<const float4*>(feat + nb * FDIM) + lane);
                s[q].x += v.x; s[q].y += v.y; s[q].z += v.z; s[q].w += v.w;
            }
        }
#pragma unroll
        for (int q = 0; q < 4; q++) {
            if (!gd[q]) s[q] = make_float4(0.f, 0.f, 0.f, 0.f);
            uint4 t;
            t.x = f2tf32(s[q].x); t.y = f2tf32(s[q].y);
            t.z = f2tf32(s[q].z); t.w = f2tf32(s[q].w);
            *reinterpret_cast<uint4*>(&As[(rbase + g + q) * AS_S + lane * 4]) = t;
        }
    }
}

__global__ __launch_bounds__(256, 3)
void fused_graphconv_kernel(
    const float* __restrict__ feat,
    const float* __restrict__ b,
    float* __restrict__ out,
    const void* __restrict__ a1,  const void* __restrict__ a2,
    const void* __restrict__ a3,  const void* __restrict__ a4,
    const void* __restrict__ a5,  const void* __restrict__ a6,
    const void* __restrict__ a7,  const void* __restrict__ a8,
    const void* __restrict__ a9,  const void* __restrict__ a10)
{
    extern __shared__ uint32_t smem[];
    uint32_t* As = smem;
    uint32_t* Bs = smem + AS_WORDS;

    const int bt = blockIdx.x;
    int seg = 0;
#pragma unroll
    for (int s = 1; s <= 10; s++)
        if (bt >= d_TCUM[s]) seg = s;

    const int rs = d_OFFS[seg] + (bt - d_TCUM[seg]) * TM;
    const int re = d_OFFS[seg + 1];
    const int segstart = d_OFFS[seg];

    const void* adj = nullptr;
    switch (seg) {
        case 1:  adj = a1;  break;  case 2:  adj = a2;  break;
        case 3:  adj = a3;  break;  case 4:  adj = a4;  break;
        case 5:  adj = a5;  break;  case 6:  adj = a6;  break;
        case 7:  adj = a7;  break;  case 8:  adj = a8;  break;
        case 9:  adj = a9;  break;  case 10: adj = a10; break;
        default: break;
    }
    const int idx64 = g_idx64;

    const int tid  = threadIdx.x;
    const int warp = tid >> 5;
    const int lane = tid & 31;
    const int wm = (warp >> 2) * 32;
    const int wn = (warp & 3) * 32;
    const int lq = lane >> 2;
    const int lr = lane & 3;
    const int bk0 = tid >> 5;
    const int bn4 = (tid & 31) * 4;

    const int mat_rel  = (seg == 0) ? 20 : 2 * (seg - 1);
    const int mat_self = (seg == 0) ? 20 : 2 * seg - 1;
    const int nSteps = (seg == 0) ? 4 : 8;

    auto issueB = [&](int mat, int s, int buf) {
        const uint32_t* src = g_wtf32 + (mat * FDIM + s * 32) * TN;
        uint32_t* dst = Bs + buf * BS_WORDS;
#pragma unroll
        for (int kk = 0; kk < 4; kk++) {
            int k = bk0 + kk * 8;
            uint32_t sa = (uint32_t)__cvta_generic_to_shared(dst + k * BS_S + bn4);
            cp_async16(sa, src + k * TN + bn4);
        }
        asm volatile("cp.async.commit_group;" ::: "memory");
    };

    auto loadA_self = [&]() {
        const int rbase = warp * 8;
        float4 v[8];
#pragma unroll
        for (int q = 0; q < 8; q++) {
            int r = rs + rbase + q;
            v[q] = make_float4(0.f, 0.f, 0.f, 0.f);
            if (r < re)
                v[q] = __ldg(reinterpret_cast<const float4*>(feat + (long long)r * FDIM) + lane);
        }
#pragma unroll
        for (int q = 0; q < 8; q++) {
            uint4 t;
            t.x = f2tf32(v[q].x); t.y = f2tf32(v[q].y);
            t.z = f2tf32(v[q].z); t.w = f2tf32(v[q].w);
            *reinterpret_cast<uint4*>(&As[(rbase + q) * AS_S + lane * 4]) = t;
        }
    };

    // ---- prologue: B(0) in flight during the first A phase ----
    issueB(mat_rel, 0, 0);
    if (seg > 0) {
        if (!idx64) {
            const int* a = (const int*)adj;
            switch (seg) {
                case 1:  gather8<1>(feat, a, rs, re, segstart, warp, lane, As); break;
                case 2:  gather8<2>(feat, a, rs, re, segstart, warp, lane, As); break;
                case 3:  gather8<3>(feat, a, rs, re, segstart, warp, lane, As); break;
                case 4:  gather8<4>(feat, a, rs, re, segstart, warp, lane, As); break;
                case 5:  gather8<5>(feat, a, rs, re, segstart, warp, lane, As); break;
                case 6:  gather8<6>(feat, a, rs, re, segstart, warp, lane, As); break;
                case 7:  gather8<7>(feat, a, rs, re, segstart, warp, lane, As); break;
                case 8:  gather8<8>(feat, a, rs, re, segstart, warp, lane, As); break;
                case 9:  gather8<9>(feat, a, rs, re, segstart, warp, lane, As); break;
                default: gather8<10>(feat, a, rs, re, segstart, warp, lane, As); break;
            }
        } else {
            gather_generic(feat, (const long long*)adj, seg, rs, re, segstart, warp, lane, As);
        }
    } else {
        loadA_self();
    }

    float acc[2][4][4];
#pragma unroll
    for (int i = 0; i < 2; i++)
#pragma unroll
        for (int j = 0; j < 4; j++)
#pragma unroll
            for (int k = 0; k < 4; k++) acc[i][j][k] = 0.f;

    for (int t = 0; t < nSteps; t++) {
        if (t == 4) {
            __syncthreads();
            loadA_self();
        }
        asm volatile("cp.async.wait_group 0;" ::: "memory");
        __syncthreads();
        if (t + 1 < nSteps) {
            int nt = t + 1;
            issueB(nt < 4 ? mat_rel : mat_self, nt & 3, nt & 1);
        }
        const uint32_t* Bbuf = Bs + (t & 1) * BS_WORDS;
        const int koA = (t & 3) * 32;
#pragma unroll
        for (int ks = 0; ks < 4; ks++) {
            const int ka = koA + ks * 8;
            const int kb = ks * 8;
            uint32_t af[2][4];
#pragma unroll
            for (int mi = 0; mi < 2; mi++) {
                int r0 = wm + 16 * mi + lq;
                int c0 = ka + lr;
                af[mi][0] = As[r0 * AS_S + c0];
                af[mi][1] = As[(r0 + 8) * AS_S + c0];
                af[mi][2] = As[r0 * AS_S + c0 + 4];
                af[mi][3] = As[(r0 + 8) * AS_S + c0 + 4];
            }
            uint32_t bf[4][2];
#pragma unroll
            for (int nj = 0; nj < 4; nj++) {
                int n0 = wn + 8 * nj + lq;
                bf[nj][0] = Bbuf[(kb + lr) * BS_S + n0];
                bf[nj][1] = Bbuf[(kb + lr + 4) * BS_S + n0];
            }
#pragma unroll
            for (int mi = 0; mi < 2; mi++)
#pragma unroll
                for (int nj = 0; nj < 4; nj++)
                    mma_tf32(acc[mi][nj], af[mi], bf[nj]);
        }
    }

    // ---- bias + relu + store ----
    float2 bv[4];
#pragma unroll
    for (int nj = 0; nj < 4; nj++) {
        int n = wn + 8 * nj + 2 * lr;
        float2 bb;
        if (seg == 0) {
            bb.x = __ldg(b + 20 * TN + n);
            bb.y = __ldg(b + 20 * TN + n + 1);
        } else {
            const float* b0 = b + (2 * (seg - 1)) * TN;
            const float* b1 = b + (2 * seg - 1) * TN;
            bb.x = __ldg(b0 + n) + __ldg(b1 + n);
            bb.y = __ldg(b0 + n + 1) + __ldg(b1 + n + 1);
        }
        bv[nj] = bb;
    }

#pragma unroll
    for (int mi = 0; mi < 2; mi++) {
        int r0 = rs + wm + 16 * mi + lq;
#pragma unroll
        for (int nj = 0; nj < 4; nj++) {
            int col = wn + 8 * nj + 2 * lr;
            const float* c = acc[mi][nj];
            if (r0 < re) {
                float2 o;
                o.x = fmaxf(c[0] + bv[nj].x, 0.f);
                o.y = fmaxf(c[1] + bv[nj].y, 0.f);
                *reinterpret_cast<float2*>(out + (long long)r0 * TN + col) = o;
            }
            if (r0 + 8 < re) {
                float2 o;
                o.x = fmaxf(c[2] + bv[nj].x, 0.f);
                o.y = fmaxf(c[3] + bv[nj].y, 0.f);
                *reinterpret_cast<float2*>(out + (long long)(r0 + 8) * TN + col) = o;
            }
        }
    }
}

extern "C" void kernel_launch(void* const* d_in, const int* in_sizes, int n_in,
                              void* d_out, int out_size)
{
    const float* feat = nullptr;
    const float* W = nullptr;
    const float* b = nullptr;
    const void* adj[11] = {nullptr};

    for (int i = 0; i < n_in; i++) {
        switch (in_sizes[i]) {
            case 64000000: feat = (const float*)d_in[i]; break;
            case 344064:   W    = (const float*)d_in[i]; break;
            case 2688:     b    = (const float*)d_in[i]; break;
            case 100000:   adj[1]  = d_in[i]; break;
            case 300000:   adj[2]  = d_in[i]; break;
            case 450000:   adj[3]  = d_in[i]; break;
            case 320000:   adj[4]  = d_in[i]; break;
            case 25000:    adj[5]  = d_in[i]; break;
            case 12000:    adj[6]  = d_in[i]; break;
            case 7000:     adj[7]  = d_in[i]; break;
            case 8000:     adj[8]  = d_in[i]; break;
            case 4500:     adj[9]  = d_in[i]; break;
            case 5000:     adj[10] = d_in[i]; break;
            default: break;
        }
    }

    static bool attr_set = false;
    if (!attr_set) {
        cudaFuncSetAttribute(fused_graphconv_kernel,
                             cudaFuncAttributeMaxDynamicSharedMemorySize, SMEM_BYTES);
        attr_set = true;
    }

    prep_kernel<<<(21 * FDIM * TN + 255) / 256, 256>>>(W, (const int*)adj[2]);

    fused_graphconv_kernel<<<TOTAL_TILES, 256, SMEM_BYTES>>>(
        feat, b, (float*)d_out,
        adj[1], adj[2], adj[3], adj[4], adj[5],
        adj[6], adj[7], adj[8], adj[9], adj[10]);
}